// round 8
// baseline (speedup 1.0000x reference)
#include <cuda_runtime.h>
#include <math.h>

// FlowLenia step: SX=SY=256, C=3, K=15, DD=5, DT=0.2, SIGMA=0.65
// out = [newA (256*256*3) | newP (256*256*15)] float32

#define NX 256
#define NC 3
#define NK 15
#define NP 8
#define DTc 0.2f
#define SIGMAc 0.65f
#define MAc 4.35f
#define INV4S2 (1.0f/(4.0f*0.65f*0.65f))
#define SUPP 1.15f
#define RST 273                  // float2 stride per FFT region (16*17 + 1 stagger)

static __device__ float2 g_fA[NC*NX*NX];     // [c][x][y] planar complex
static __device__ float2 g_G [NX*NX*NP];     // [x][y][j]
static __device__ float  g_UcA[NX*NX*NC];    // partial chansum k 0..7   [y][x][c]
static __device__ float  g_UcB[NX*NX*NC];    // partial chansum k 8..14  [y][x][c]

__device__ __forceinline__ float2 f2add(float2 a, float2 b){ return make_float2(a.x+b.x, a.y+b.y); }
__device__ __forceinline__ float2 f2sub(float2 a, float2 b){ return make_float2(a.x-b.x, a.y-b.y); }

template<bool INV>
__device__ __forceinline__ float2 cmulc(float2 a, float wr, float wi) {
    float yi = INV ? -wi : wi;
    return make_float2(a.x*wr - a.y*yi, a.x*yi + a.y*wr);
}
template<bool INV>
__device__ __forceinline__ float2 cmulv(float2 a, float2 w) {
    float wi = INV ? -w.y : w.y;
    return make_float2(a.x*w.x - a.y*wi, a.x*wi + a.y*w.x);
}

// In-register 16-point DFT, natural order in and out. X[k]=sum x[n] W16^{nk} (conj if INV).
template<bool INV>
__device__ __forceinline__ void dft16(float2* v) {
    const float C1 = 0.9238795325112867f;   // cos(pi/8)
    const float S1 = 0.3826834323650898f;   // sin(pi/8)
    const float R  = 0.7071067811865476f;
    float2 t[16];
#pragma unroll
    for (int a = 0; a < 4; a++) {
        float2 x0 = v[a], x1 = v[a+4], x2 = v[a+8], x3 = v[a+12];
        float2 e0 = f2add(x0,x2), e1 = f2sub(x0,x2);
        float2 o0 = f2add(x1,x3), o1 = f2sub(x1,x3);
        float2 io1 = INV ? make_float2(-o1.y, o1.x) : make_float2(o1.y, -o1.x);
        t[a*4+0] = f2add(e0,o0);
        t[a*4+1] = f2add(e1,io1);
        t[a*4+2] = f2sub(e0,o0);
        t[a*4+3] = f2sub(e1,io1);
    }
    t[4+1]  = cmulc<INV>(t[4+1],  C1, -S1);   // W16^1
    t[4+2]  = cmulc<INV>(t[4+2],  R,  -R );   // W16^2
    t[4+3]  = cmulc<INV>(t[4+3],  S1, -C1);   // W16^3
    t[8+1]  = cmulc<INV>(t[8+1],  R,  -R );   // W16^2
    t[8+2]  = cmulc<INV>(t[8+2],  0.f,-1.f);  // W16^4
    t[8+3]  = cmulc<INV>(t[8+3], -R,  -R );   // W16^6
    t[12+1] = cmulc<INV>(t[12+1], S1, -C1);   // W16^3
    t[12+2] = cmulc<INV>(t[12+2],-R,  -R );   // W16^6
    t[12+3] = cmulc<INV>(t[12+3],-C1,  S1);   // W16^9
#pragma unroll
    for (int c = 0; c < 4; c++) {
        float2 x0 = t[c], x1 = t[4+c], x2 = t[8+c], x3 = t[12+c];
        float2 e0 = f2add(x0,x2), e1 = f2sub(x0,x2);
        float2 o0 = f2add(x1,x3), o1 = f2sub(x1,x3);
        float2 io1 = INV ? make_float2(-o1.y, o1.x) : make_float2(o1.y, -o1.x);
        v[c+0]  = f2add(e0,o0);
        v[c+4]  = f2add(e1,io1);
        v[c+8]  = f2sub(e0,o0);
        v[c+12] = f2sub(e1,io1);
    }
}

__device__ __forceinline__ void tw_init_smem(float2* tw, int tid, int nthr) {
    for (int j = tid; j < 256; j += nthr) {
        float sv, cv;
        sincospif(-(float)j * (1.0f/128.0f), &sv, &cv);
        tw[j] = make_float2(cv, sv);
    }
}

// Phase 1 for one FFT region: thread n1 reads its row [17*n1 + n2], DFT16 over n2,
// twiddle W256^{n1*k2}, writes back [17*n1 + k2]. Own-row only: no cross-thread hazard.
template<bool INV>
__device__ __forceinline__ void fft_phase1(float2* s, const float2* tw, int n1) {
    float2 v[16];
#pragma unroll
    for (int n2 = 0; n2 < 16; n2++) v[n2] = s[17*n1 + n2];
    dft16<INV>(v);
#pragma unroll
    for (int k2 = 1; k2 < 16; k2++) v[k2] = cmulv<INV>(v[k2], tw[n1*k2]);
#pragma unroll
    for (int k2 = 0; k2 < 16; k2++) s[17*n1 + k2] = v[k2];
}
// Phase 2: thread k2 reads column [17*n1 + k2], DFT16 over n1 -> X[k2 + 16*k1] = v[k1].
template<bool INV>
__device__ __forceinline__ void fft_phase2(const float2* s, int k2, float2* v) {
#pragma unroll
    for (int n1 = 0; n1 < 16; n1++) v[n1] = s[17*n1 + k2];
    dft16<INV>(v);
}

// S1: FFT along y. grid (64, 3), block 64 thr = 4 row-FFTs.
__global__ void s1_fft_y(const float* __restrict__ A) {
    __shared__ float2 sm[4*RST];
    __shared__ float2 tw[256];
    int x0 = blockIdx.x*4, c = blockIdx.y, tid = threadIdx.x;
    tw_init_smem(tw, tid, 64);
    for (int e = tid; e < 1024; e += 64) {
        int f = e >> 8, i = e & 255;
        sm[f*RST + 17*(i & 15) + (i >> 4)] = make_float2(A[((x0+f)*NX + i)*NC + c], 0.f);
    }
    __syncthreads();
    int f = tid >> 4, n1 = tid & 15;
    fft_phase1<false>(sm + f*RST, tw, n1);
    __syncthreads();
    float2 v[16];
    int k2 = n1;
    fft_phase2<false>(sm + f*RST, k2, v);
    float2* out = g_fA + c*NX*NX + (x0+f)*NX;
#pragma unroll
    for (int k1 = 0; k1 < 16; k1++) out[k2 + 16*k1] = v[k1];
}

// S2: FFT along x. grid (64, 3), block 64 thr = 4 column-FFTs.
__global__ void s2_fft_x() {
    __shared__ float2 sm[4*RST];
    __shared__ float2 tw[256];
    int y0 = blockIdx.x*4, c = blockIdx.y, tid = threadIdx.x;
    tw_init_smem(tw, tid, 64);
    float2* base = g_fA + c*NX*NX;
    for (int e = tid; e < 1024; e += 64) {
        int f = e & 3, xx = e >> 2;
        sm[f*RST + 17*(xx & 15) + (xx >> 4)] = base[xx*NX + y0 + f];
    }
    __syncthreads();
    int f = tid >> 4, n1 = tid & 15;
    fft_phase1<false>(sm + f*RST, tw, n1);
    __syncthreads();
    float2 v[16];
    fft_phase2<false>(sm + f*RST, n1, v);
    // stage outputs to smem (slot 17*k2 + k1 == transposed index of xx=k2+16k1)
#pragma unroll
    for (int k1 = 0; k1 < 16; k1++) sm[f*RST + 17*n1 + k1] = v[k1];
    __syncthreads();
    for (int e = tid; e < 1024; e += 64) {
        int f2 = e & 3, xx = e >> 2;
        base[xx*NX + y0 + f2] = sm[f2*RST + 17*(xx & 15) + (xx >> 4)];
    }
}

// S3: multiply by fK + inverse FFT along y. grid (256, 2), block 64 thr = 4 pair-FFTs.
__global__ void s3_mul_ifft_y(const float* __restrict__ fKr, const float* __restrict__ fKi) {
    __shared__ float2 sm[4*RST];
    __shared__ float2 sfA[NC*NX];
    __shared__ float2 tw[256];
    int x = blockIdx.x, j0 = blockIdx.y*4, tid = threadIdx.x;
    tw_init_smem(tw, tid, 64);
    for (int e = tid; e < NC*NX; e += 64) {
        int c = e >> 8, y = e & 255;
        sfA[c*NX + y] = g_fA[c*NX*NX + x*NX + y];
    }
    __syncthreads();
    for (int e = tid; e < 1024; e += 64) {
        int jj = e & 3, y = e >> 2;
        int k1 = 2*(j0 + jj);
        int idx = (x*NX + y)*NK;
        float2 a1 = sfA[(k1 % NC)*NX + y];
        float kr = fKr[idx + k1], ki = fKi[idx + k1];
        float2 H = make_float2(kr*a1.x - ki*a1.y, kr*a1.y + ki*a1.x);
        if (k1 + 1 < NK) {
            float2 a2 = sfA[((k1+1) % NC)*NX + y];
            float kr2 = fKr[idx + k1 + 1], ki2 = fKi[idx + k1 + 1];
            float zr = kr2*a2.x - ki2*a2.y;
            float zi = kr2*a2.y + ki2*a2.x;
            H.x -= zi; H.y += zr;
        }
        sm[jj*RST + 17*(y & 15) + (y >> 4)] = H;
    }
    __syncthreads();
    int jj = tid >> 4, n1 = tid & 15;
    fft_phase1<true>(sm + jj*RST, tw, n1);
    __syncthreads();
    float2 v[16];
    fft_phase2<true>(sm + jj*RST, n1, v);
#pragma unroll
    for (int k1 = 0; k1 < 16; k1++) sm[jj*RST + 17*n1 + k1] = v[k1];
    __syncthreads();
    for (int e = tid; e < 1024; e += 64) {
        int j2 = e & 3, y = e >> 2;
        g_G[(x*NX + y)*NP + j0 + j2] = sm[j2*RST + 17*(y & 15) + (y >> 4)];
    }
}

// S4: inverse FFT along x + growth*P + partial chansum. grid (256, 2), block 64 thr.
__global__ void s4_ifft_x_growth(const float* __restrict__ P,
                                 const float* __restrict__ mArr,
                                 const float* __restrict__ sArr) {
    __shared__ float2 sm[4*RST];
    __shared__ float  sP[NX*9];
    __shared__ float2 tw[256];
    int y = blockIdx.x, bp = blockIdx.y, tid = threadIdx.x;
    int k0 = bp*8;
    tw_init_smem(tw, tid, 64);
    for (int e = tid; e < 1024; e += 64) {
        int jj = e & 3, xx = e >> 2;
        sm[jj*RST + 17*(xx & 15) + (xx >> 4)] = g_G[(xx*NX + y)*NP + bp*4 + jj];
    }
    for (int e = tid; e < NX*8; e += 64) {
        int xx = e >> 3, kk = e & 7;
        int k = k0 + kk;
        sP[xx*9 + kk] = (k < NK) ? P[(xx*NX + y)*NK + k] : 0.f;
    }
    __syncthreads();
    int jj = tid >> 4, k2 = tid & 15;
    fft_phase1<true>(sm + jj*RST, tw, k2);
    __syncthreads();
    float2 v[16];
    fft_phase2<true>(sm + jj*RST, k2, v);

    int ka = k0 + 2*jj, kb = ka + 1;
    float m1 = mArr[ka], s1 = sArr[ka];
    float inv1 = 1.f / (2.f * s1 * s1);
    float m2 = 0.f, inv2 = 0.f;
    if (kb < NK) { m2 = mArr[kb]; float s2 = sArr[kb]; inv2 = 1.f / (2.f * s2 * s2); }
#pragma unroll
    for (int k1 = 0; k1 < 16; k1++) {
        int xx = k2 + 16*k1;
        float u1 = v[k1].x * (1.f / 65536.f);
        float d1 = u1 - m1;
        sP[xx*9 + 2*jj] *= (2.f * expf(-d1*d1*inv1) - 1.f);
        if (kb < NK) {
            float u2 = v[k1].y * (1.f / 65536.f);
            float d2 = u2 - m2;
            sP[xx*9 + 2*jj + 1] *= (2.f * expf(-d2*d2*inv2) - 1.f);
        }
    }
    __syncthreads();
    float* out = bp ? g_UcB : g_UcA;
    for (int e = tid; e < NX*NC; e += 64) {
        int xx = e / NC, c = e - xx*NC;
        float sum = 0.f;
#pragma unroll
        for (int kk = 0; kk < 8; kk++) {
            int k = k0 + kk;
            if (k < NK && (k % 3) == c) sum += sP[xx*9 + kk];
        }
        out[(y*NX + xx)*NC + c] = sum;
    }
}

// Fused sobel + mus + reintegration (unchanged from R7 structure).
#define TXo 8
#define TYo 16
__global__ void fused_flow(const float* __restrict__ A, const float* __restrict__ P,
                           float* __restrict__ outA, float* __restrict__ outP) {
    __shared__ __align__(16) float rec[240*24];
    __shared__ float sUc[14*22*3];
    __shared__ float sAs[14*22];
    int tid = threadIdx.x;
    int y0 = blockIdx.x * TYo, x0 = blockIdx.y * TXo;

    for (int e = tid; e < 14*22; e += 128) {
        int i = e / 22, j = e - i*22;
        int gx = x0 - 3 + i, gy = y0 - 3 + j;
        float u0 = 0.f, u1 = 0.f, u2 = 0.f, as = 0.f;
        if (gx >= 0 && gx < NX && gy >= 0 && gy < NX) {
            int bU = (gy*NX + gx)*NC;
            u0 = g_UcA[bU]   + g_UcB[bU];
            u1 = g_UcA[bU+1] + g_UcB[bU+1];
            u2 = g_UcA[bU+2] + g_UcB[bU+2];
            int bA = (gx*NX + gy)*NC;
            as = A[bA] + A[bA+1] + A[bA+2];
        }
        sUc[e*3+0] = u0; sUc[e*3+1] = u1; sUc[e*3+2] = u2;
        sAs[e] = as;
    }
    __syncthreads();

    for (int e = tid; e < 240; e += 128) {
        int i = e / 20, j = e - i*20;
        int gx = x0 - 2 + i, gy = y0 - 2 + j;
        float* r = rec + e*24;
        if (gx >= 0 && gx < NX && gy >= 0 && gy < NX) {
            int si = i + 1, sj = j + 1;
            int rm = (si-1)*22 + sj, rp = (si+1)*22 + sj, r0 = si*22 + sj;
            float cg0 = (sAs[rp-1] + 2.f*sAs[rp] + sAs[rp+1])
                      - (sAs[rm-1] + 2.f*sAs[rm] + sAs[rm+1]);
            float cg1 = (sAs[rm+1] + 2.f*sAs[r0+1] + sAs[rp+1])
                      - (sAs[rm-1] + 2.f*sAs[r0-1] + sAs[rp-1]);
            int bA = (gx*NX + gy)*NC;
            float p0 = gx + 0.5f, p1 = gy + 0.5f;
#pragma unroll
            for (int c = 0; c < NC; c++) {
                float f0 = (sUc[(rp-1)*3+c] + 2.f*sUc[rp*3+c] + sUc[(rp+1)*3+c])
                         - (sUc[(rm-1)*3+c] + 2.f*sUc[rm*3+c] + sUc[(rm+1)*3+c]);
                float f1 = (sUc[(rm+1)*3+c] + 2.f*sUc[(r0+1)*3+c] + sUc[(rp+1)*3+c])
                         - (sUc[(rm-1)*3+c] + 2.f*sUc[(r0-1)*3+c] + sUc[(rp-1)*3+c]);
                float ac = A[bA + c];
                float ah = ac * 0.5f;
                float alpha = fminf(ah*ah, 1.f);
                float F0 = fminf(fmaxf(f0*(1.f-alpha) - cg0*alpha, -MAc), MAc);
                float F1 = fminf(fmaxf(f1*(1.f-alpha) - cg1*alpha, -MAc), MAc);
                r[c]   = fminf(fmaxf(p0 + DTc*F0, SIGMAc), (float)NX - SIGMAc);
                r[3+c] = fminf(fmaxf(p1 + DTc*F1, SIGMAc), (float)NX - SIGMAc);
                r[6+c] = ac;
            }
        } else {
#pragma unroll
            for (int c = 0; c < 6; c++) r[c] = -1e9f;
            r[6] = r[7] = r[8] = 0.f;
        }
    }
    for (int e = tid; e < 240*NK; e += 128) {
        int pix = e / NK, k = e - pix*NK;
        int i = pix / 20, j = pix - i*20;
        int gx = x0 - 2 + i, gy = y0 - 2 + j;
        float vv = 0.f;
        if (gx >= 0 && gx < NX && gy >= 0 && gy < NX)
            vv = P[(gx*NX + gy)*NK + k];
        rec[pix*24 + 9 + k] = vv;
    }
    __syncthreads();

    int ty = tid & 15, tx = tid >> 4;
    int x = x0 + tx, y = y0 + ty;
    float p0 = x + 0.5f, p1 = y + 0.5f;
    float accA0 = 0.f, accA1 = 0.f, accA2 = 0.f, accW = 0.f;
    float accP[NK];
#pragma unroll
    for (int k = 0; k < NK; k++) accP[k] = 0.f;

#pragma unroll
    for (int dx = -2; dx <= 2; dx++) {
#pragma unroll
        for (int dy = -2; dy <= 2; dy++) {
            int ridx = (tx + 2 - dx)*20 + (ty + 2 - dy);
            const float4* r4 = (const float4*)(rec + ridx*24);
            float4 q0 = r4[0];
            float4 q1 = r4[1];
            float4 q2 = r4[2];
            float s00 = fminf(fmaxf(SUPP - fabsf(p0 - q0.x), 0.f), 1.f);
            float s01 = fminf(fmaxf(SUPP - fabsf(p0 - q0.y), 0.f), 1.f);
            float s02 = fminf(fmaxf(SUPP - fabsf(p0 - q0.z), 0.f), 1.f);
            float s10 = fminf(fmaxf(SUPP - fabsf(p1 - q0.w), 0.f), 1.f);
            float s11 = fminf(fmaxf(SUPP - fabsf(p1 - q1.x), 0.f), 1.f);
            float s12 = fminf(fmaxf(SUPP - fabsf(p1 - q1.y), 0.f), 1.f);
            float v0 = q1.z * (s00*s10*INV4S2);
            float v1 = q1.w * (s01*s11*INV4S2);
            float v2 = q2.x * (s02*s12*INV4S2);
            accA0 += v0; accA1 += v1; accA2 += v2;
            float suma = v0 + v1 + v2;
            if (suma > 0.f) {
                float w = expf(suma) - 1.f;
                accW += w;
                accP[0] += w*q2.y; accP[1] += w*q2.z; accP[2] += w*q2.w;
                float4 q3 = r4[3], q4 = r4[4], q5 = r4[5];
                accP[3] += w*q3.x; accP[4] += w*q3.y; accP[5] += w*q3.z; accP[6] += w*q3.w;
                accP[7] += w*q4.x; accP[8] += w*q4.y; accP[9] += w*q4.z; accP[10] += w*q4.w;
                accP[11] += w*q5.x; accP[12] += w*q5.y; accP[13] += w*q5.z; accP[14] += w*q5.w;
            }
        }
    }

    int o = x*NX + y;
    outA[o*NC + 0] = accA0; outA[o*NC + 1] = accA1; outA[o*NC + 2] = accA2;
    float inv = 1.f / (accW + 1e-10f);
#pragma unroll
    for (int k = 0; k < NK; k++) outP[o*NK + k] = accP[k] * inv;
}

extern "C" void kernel_launch(void* const* d_in, const int* in_sizes, int n_in,
                              void* d_out, int out_size) {
    const float* A   = (const float*)d_in[0];
    const float* P   = (const float*)d_in[1];
    const float* fKr = (const float*)d_in[2];
    const float* fKi = (const float*)d_in[3];
    const float* m   = (const float*)d_in[4];
    const float* s   = (const float*)d_in[5];
    float* outA = (float*)d_out;
    float* outP = outA + NX*NX*NC;

    s1_fft_y         <<<dim3(64, NC), 64>>>(A);
    s2_fft_x         <<<dim3(64, NC), 64>>>();
    s3_mul_ifft_y    <<<dim3(NX, 2), 64>>>(fKr, fKi);
    s4_ifft_x_growth <<<dim3(NX, 2), 64>>>(P, m, s);
    fused_flow       <<<dim3(16, 32), 128>>>(A, P, outA, outP);
}

// round 9
// speedup vs baseline: 1.1730x; 1.1730x over previous
#include <cuda_runtime.h>
#include <math.h>

// FlowLenia step: SX=SY=256, C=3, K=15, DD=5, DT=0.2, SIGMA=0.65
// out = [newA (256*256*3) | newP (256*256*15)] float32

#define NX 256
#define NC 3
#define NK 15
#define NP 8
#define DTc 0.2f
#define SIGMAc 0.65f
#define MAc 4.35f
#define INV4S2 (1.0f/(4.0f*0.65f*0.65f))
#define SUPP 1.15f
#define IDX(i) ((i) + ((i) >> 4))
#define FSTR 273

static __device__ float2 g_fA[NC*NX*NX];     // [c][x][y]
static __device__ float2 g_G [NX*NX*NP];     // [x][y][j]
static __device__ float  g_UcA[NX*NX*NC];    // partial chansum k 0..7   [y][x][c]
static __device__ float  g_UcB[NX*NX*NC];    // partial chansum k 8..14  [y][x][c]

__device__ __forceinline__ int rev4(int i) {
    return ((i & 3) << 6) | ((i & 0xC) << 2) | ((i >> 2) & 0xC) | ((i >> 6) & 3);
}
__device__ __forceinline__ float2 cmul(float2 a, float2 b) {
    return make_float2(a.x*b.x - a.y*b.y, a.x*b.y + a.y*b.x);
}
__device__ __forceinline__ void tw_init_smem(float2* tw, int tid, int nthr) {
    for (int j = tid; j < 256; j += nthr) {
        float sv, cv;
        sincospif(-(float)j * (1.0f/128.0f), &sv, &cv);
        tw[j] = make_float2(cv, sv);
    }
}

// 256-pt radix-4 DIT FFT, 128 threads per FFT: each butterfly group is computed
// by TWO adjacent lanes (h = t&1); both load the group's 4 inputs (broadcast),
// each writes 2 outputs. Adjacent lanes are in one warp -> SIMT lockstep orders
// group loads before either lane's stores; groups partition slots -> race-free.
// __syncthreads at top of each stage (covers producer writes) and at the end.
template<bool INV>
__device__ __forceinline__ void fft256_r4d(float2* s, const float2* tw, int t) {
    int h = t & 1, tt = t >> 1;
#pragma unroll
    for (int m = 0; m < 4; m++) {
        __syncthreads();
        int q    = 1 << (2*m);
        int p    = tt & (q - 1);
        int grp  = tt >> (2*m);
        int base = grp*(q << 2) + p;
        int ts   = 64 >> (2*m);
        float2 w1 = tw[p*ts];
        float2 w2 = tw[2*p*ts];
        float2 w3 = tw[3*p*ts];
        if (INV) { w1.y = -w1.y; w2.y = -w2.y; w3.y = -w3.y; }
        float2 x0 = s[IDX(base)];
        float2 t1 = cmul(s[IDX(base +   q)], w1);
        float2 t2 = cmul(s[IDX(base + 2*q)], w2);
        float2 t3 = cmul(s[IDX(base + 3*q)], w3);
        float2 b0 = make_float2(x0.x + t2.x, x0.y + t2.y);
        float2 b1 = make_float2(x0.x - t2.x, x0.y - t2.y);
        float2 b2 = make_float2(t1.x + t3.x, t1.y + t3.y);
        float2 b3 = make_float2(t1.x - t3.x, t1.y - t3.y);
        float2 ib3 = INV ? make_float2(-b3.y, b3.x) : make_float2(b3.y, -b3.x);
        if (h == 0) {
            s[IDX(base)]       = make_float2(b0.x + b2.x, b0.y + b2.y);
            s[IDX(base +   q)] = make_float2(b1.x + ib3.x, b1.y + ib3.y);
        } else {
            s[IDX(base + 2*q)] = make_float2(b0.x - b2.x, b0.y - b2.y);
            s[IDX(base + 3*q)] = make_float2(b1.x - ib3.x, b1.y - ib3.y);
        }
    }
    __syncthreads();
}

// S1: FFT along y. grid (256, 3), block 128 = one FFT.
__global__ void s1_fft_y(const float* __restrict__ A) {
    __shared__ float2 s[FSTR];
    __shared__ float2 tw[256];
    int x = blockIdx.x, c = blockIdx.y, t = threadIdx.x;
    tw_init_smem(tw, t, 128);
#pragma unroll
    for (int jj = 0; jj < 2; jj++) {
        int i = t + 128*jj;
        s[IDX(rev4(i))] = make_float2(A[(x*NX + i)*NC + c], 0.f);
    }
    fft256_r4d<false>(s, tw, t);
#pragma unroll
    for (int jj = 0; jj < 2; jj++) {
        int i = t + 128*jj;
        g_fA[c*NX*NX + x*NX + i] = s[IDX(i)];
    }
}

// S2: FFT along x, 4 ky-columns per block. grid (64, 3), block (128, 4).
__global__ void s2_fft_x() {
    __shared__ float2 sm[4][FSTR];
    __shared__ float2 tw[256];
    int c = blockIdx.y, y0 = blockIdx.x * 4;
    int t = threadIdx.x, yl = threadIdx.y;
    int tid = yl*128 + t;
    tw_init_smem(tw, tid, 512);
    int base = c*NX*NX;
    for (int e = tid; e < 1024; e += 512) {
        int x = e >> 2, yy = e & 3;
        sm[yy][IDX(rev4(x))] = g_fA[base + x*NX + y0 + yy];
    }
    fft256_r4d<false>(sm[yl], tw, t);
    for (int e = tid; e < 1024; e += 512) {
        int x = e >> 2, yy = e & 3;
        g_fA[base + x*NX + y0 + yy] = sm[yy][IDX(x)];
    }
}

// S3: multiply by fK + inverse FFT along y. grid (256, 2), block (128, 4) = 4 pairs.
__global__ void s3_mul_ifft_y(const float* __restrict__ fKr, const float* __restrict__ fKi) {
    __shared__ float2 sm[4][FSTR];
    __shared__ float2 sfA[NC][NX];
    __shared__ float2 tw[256];
    int x = blockIdx.x, t = threadIdx.x, jl = threadIdx.y;
    int j0 = blockIdx.y * 4;
    int tid = jl*128 + t;
    tw_init_smem(tw, tid, 512);
    for (int e = tid; e < NC*NX; e += 512) {
        int c = e >> 8, y = e & 255;
        sfA[c][y] = g_fA[c*NX*NX + x*NX + y];
    }
    __syncthreads();
    for (int e = tid; e < 1024; e += 512) {
        int y = e >> 2, jj = e & 3;
        int k1 = 2*(j0 + jj);
        int idx = (x*NX + y)*NK;
        float2 a1 = sfA[k1 % NC][y];
        float kr = fKr[idx + k1], ki = fKi[idx + k1];
        float2 H = make_float2(kr*a1.x - ki*a1.y, kr*a1.y + ki*a1.x);
        if (k1 + 1 < NK) {
            float2 a2 = sfA[(k1+1) % NC][y];
            float kr2 = fKr[idx + k1 + 1], ki2 = fKi[idx + k1 + 1];
            float zr = kr2*a2.x - ki2*a2.y;
            float zi = kr2*a2.y + ki2*a2.x;
            H.x -= zi; H.y += zr;
        }
        sm[jj][IDX(rev4(y))] = H;
    }
    fft256_r4d<true>(sm[jl], tw, t);   // leading stage sync covers staging
    for (int e = tid; e < 1024; e += 512) {
        int y = e >> 2, jj = e & 3;
        g_G[(x*NX + y)*NP + j0 + jj] = sm[jj][IDX(y)];
    }
}

// S4: inverse FFT along x + growth*P + partial chansum. grid (256, 2), block (128, 4).
__global__ void s4_ifft_x_growth(const float* __restrict__ P,
                                 const float* __restrict__ mArr,
                                 const float* __restrict__ sArr) {
    __shared__ float2 sm[4][FSTR];
    __shared__ float  sP[NX*9];
    __shared__ float2 tw[256];
    int y = blockIdx.x, bp = blockIdx.y;
    int k0 = bp * 8;
    int t = threadIdx.x, jl = threadIdx.y;
    int tid = jl*128 + t;
    tw_init_smem(tw, tid, 512);
    for (int e = tid; e < 1024; e += 512) {
        int xx = e >> 2, jj = e & 3;
        sm[jj][IDX(rev4(xx))] = g_G[(xx*NX + y)*NP + bp*4 + jj];
    }
    for (int e = tid; e < NX*8; e += 512) {
        int xx = e >> 3, kk = e & 7;
        int k = k0 + kk;
        sP[xx*9 + kk] = (k < NK) ? P[(xx*NX + y)*NK + k] : 0.f;
    }
    fft256_r4d<true>(sm[jl], tw, t);   // leading stage sync covers staging

    int ka = k0 + 2*jl, kb = ka + 1;
    float m1 = mArr[ka], s1 = sArr[ka];
    float inv1 = 1.f / (2.f * s1 * s1);
    float m2 = 0.f, inv2 = 0.f;
    if (kb < NK) { m2 = mArr[kb]; float s2 = sArr[kb]; inv2 = 1.f / (2.f * s2 * s2); }
#pragma unroll
    for (int jj2 = 0; jj2 < 2; jj2++) {
        int xx = t + 128*jj2;
        float2 v = sm[jl][IDX(xx)];
        float u1 = v.x * (1.f / 65536.f);
        float d1 = u1 - m1;
        sP[xx*9 + 2*jl] *= (2.f * expf(-d1*d1*inv1) - 1.f);
        if (kb < NK) {
            float u2 = v.y * (1.f / 65536.f);
            float d2 = u2 - m2;
            sP[xx*9 + 2*jl + 1] *= (2.f * expf(-d2*d2*inv2) - 1.f);
        }
    }
    __syncthreads();
    float* out = bp ? g_UcB : g_UcA;
    for (int e = tid; e < NX*NC; e += 512) {
        int xx = e / NC, c = e - xx*NC;
        float sum = 0.f;
#pragma unroll
        for (int kk = 0; kk < 8; kk++) {
            int k = k0 + kk;
            if (k < NK && (k % 3) == c) sum += sP[xx*9 + kk];
        }
        out[(y*NX + xx)*NC + c] = sum;
    }
}

// Fused sobel + mus + reintegration. Output tile 8(x) x 16(y) per 128-thread block.
#define TXo 8
#define TYo 16
__global__ void fused_flow(const float* __restrict__ A, const float* __restrict__ P,
                           float* __restrict__ outA, float* __restrict__ outP) {
    __shared__ __align__(16) float rec[240*24];
    __shared__ float sUc[14*22*3];
    __shared__ float sAs[14*22];
    int tid = threadIdx.x;
    int y0 = blockIdx.x * TYo, x0 = blockIdx.y * TXo;

    for (int e = tid; e < 14*22; e += 128) {
        int i = e / 22, j = e - i*22;
        int gx = x0 - 3 + i, gy = y0 - 3 + j;
        float u0 = 0.f, u1 = 0.f, u2 = 0.f, as = 0.f;
        if (gx >= 0 && gx < NX && gy >= 0 && gy < NX) {
            int bU = (gy*NX + gx)*NC;
            u0 = g_UcA[bU]   + g_UcB[bU];
            u1 = g_UcA[bU+1] + g_UcB[bU+1];
            u2 = g_UcA[bU+2] + g_UcB[bU+2];
            int bA = (gx*NX + gy)*NC;
            as = A[bA] + A[bA+1] + A[bA+2];
        }
        sUc[e*3+0] = u0; sUc[e*3+1] = u1; sUc[e*3+2] = u2;
        sAs[e] = as;
    }
    __syncthreads();

    for (int e = tid; e < 240; e += 128) {
        int i = e / 20, j = e - i*20;
        int gx = x0 - 2 + i, gy = y0 - 2 + j;
        float* r = rec + e*24;
        if (gx >= 0 && gx < NX && gy >= 0 && gy < NX) {
            int si = i + 1, sj = j + 1;
            int rm = (si-1)*22 + sj, rp = (si+1)*22 + sj, r0 = si*22 + sj;
            float cg0 = (sAs[rp-1] + 2.f*sAs[rp] + sAs[rp+1])
                      - (sAs[rm-1] + 2.f*sAs[rm] + sAs[rm+1]);
            float cg1 = (sAs[rm+1] + 2.f*sAs[r0+1] + sAs[rp+1])
                      - (sAs[rm-1] + 2.f*sAs[r0-1] + sAs[rp-1]);
            int bA = (gx*NX + gy)*NC;
            float p0 = gx + 0.5f, p1 = gy + 0.5f;
#pragma unroll
            for (int c = 0; c < NC; c++) {
                float f0 = (sUc[(rp-1)*3+c] + 2.f*sUc[rp*3+c] + sUc[(rp+1)*3+c])
                         - (sUc[(rm-1)*3+c] + 2.f*sUc[rm*3+c] + sUc[(rm+1)*3+c]);
                float f1 = (sUc[(rm+1)*3+c] + 2.f*sUc[(r0+1)*3+c] + sUc[(rp+1)*3+c])
                         - (sUc[(rm-1)*3+c] + 2.f*sUc[(r0-1)*3+c] + sUc[(rp-1)*3+c]);
                float ac = A[bA + c];
                float ah = ac * 0.5f;
                float alpha = fminf(ah*ah, 1.f);
                float F0 = fminf(fmaxf(f0*(1.f-alpha) - cg0*alpha, -MAc), MAc);
                float F1 = fminf(fmaxf(f1*(1.f-alpha) - cg1*alpha, -MAc), MAc);
                r[c]   = fminf(fmaxf(p0 + DTc*F0, SIGMAc), (float)NX - SIGMAc);
                r[3+c] = fminf(fmaxf(p1 + DTc*F1, SIGMAc), (float)NX - SIGMAc);
                r[6+c] = ac;
            }
        } else {
#pragma unroll
            for (int c = 0; c < 6; c++) r[c] = -1e9f;
            r[6] = r[7] = r[8] = 0.f;
        }
    }
    for (int e = tid; e < 240*NK; e += 128) {
        int pix = e / NK, k = e - pix*NK;
        int i = pix / 20, j = pix - i*20;
        int gx = x0 - 2 + i, gy = y0 - 2 + j;
        float vv = 0.f;
        if (gx >= 0 && gx < NX && gy >= 0 && gy < NX)
            vv = P[(gx*NX + gy)*NK + k];
        rec[pix*24 + 9 + k] = vv;
    }
    __syncthreads();

    int ty = tid & 15, tx = tid >> 4;
    int x = x0 + tx, y = y0 + ty;
    float p0 = x + 0.5f, p1 = y + 0.5f;
    float accA0 = 0.f, accA1 = 0.f, accA2 = 0.f, accW = 0.f;
    float accP[NK];
#pragma unroll
    for (int k = 0; k < NK; k++) accP[k] = 0.f;

#pragma unroll
    for (int dx = -2; dx <= 2; dx++) {
#pragma unroll
        for (int dy = -2; dy <= 2; dy++) {
            int ridx = (tx + 2 - dx)*20 + (ty + 2 - dy);
            const float4* r4 = (const float4*)(rec + ridx*24);
            float4 q0 = r4[0];
            float4 q1 = r4[1];
            float4 q2 = r4[2];
            float s00 = fminf(fmaxf(SUPP - fabsf(p0 - q0.x), 0.f), 1.f);
            float s01 = fminf(fmaxf(SUPP - fabsf(p0 - q0.y), 0.f), 1.f);
            float s02 = fminf(fmaxf(SUPP - fabsf(p0 - q0.z), 0.f), 1.f);
            float s10 = fminf(fmaxf(SUPP - fabsf(p1 - q0.w), 0.f), 1.f);
            float s11 = fminf(fmaxf(SUPP - fabsf(p1 - q1.x), 0.f), 1.f);
            float s12 = fminf(fmaxf(SUPP - fabsf(p1 - q1.y), 0.f), 1.f);
            float v0 = q1.z * (s00*s10*INV4S2);
            float v1 = q1.w * (s01*s11*INV4S2);
            float v2 = q2.x * (s02*s12*INV4S2);
            accA0 += v0; accA1 += v1; accA2 += v2;
            float suma = v0 + v1 + v2;
            if (suma > 0.f) {
                float w = expf(suma) - 1.f;
                accW += w;
                accP[0] += w*q2.y; accP[1] += w*q2.z; accP[2] += w*q2.w;
                float4 q3 = r4[3], q4 = r4[4], q5 = r4[5];
                accP[3] += w*q3.x; accP[4] += w*q3.y; accP[5] += w*q3.z; accP[6] += w*q3.w;
                accP[7] += w*q4.x; accP[8] += w*q4.y; accP[9] += w*q4.z; accP[10] += w*q4.w;
                accP[11] += w*q5.x; accP[12] += w*q5.y; accP[13] += w*q5.z; accP[14] += w*q5.w;
            }
        }
    }

    int o = x*NX + y;
    outA[o*NC + 0] = accA0; outA[o*NC + 1] = accA1; outA[o*NC + 2] = accA2;
    float inv = 1.f / (accW + 1e-10f);
#pragma unroll
    for (int k = 0; k < NK; k++) outP[o*NK + k] = accP[k] * inv;
}

extern "C" void kernel_launch(void* const* d_in, const int* in_sizes, int n_in,
                              void* d_out, int out_size) {
    const float* A   = (const float*)d_in[0];
    const float* P   = (const float*)d_in[1];
    const float* fKr = (const float*)d_in[2];
    const float* fKi = (const float*)d_in[3];
    const float* m   = (const float*)d_in[4];
    const float* s   = (const float*)d_in[5];
    float* outA = (float*)d_out;
    float* outP = outA + NX*NX*NC;

    s1_fft_y         <<<dim3(NX, NC), 128>>>(A);
    s2_fft_x         <<<dim3(64, NC), dim3(128, 4)>>>();
    s3_mul_ifft_y    <<<dim3(NX, 2), dim3(128, 4)>>>(fKr, fKi);
    s4_ifft_x_growth <<<dim3(NX, 2), dim3(128, 4)>>>(P, m, s);
    fused_flow       <<<dim3(16, 32), 128>>>(A, P, outA, outP);
}

// round 10
// speedup vs baseline: 1.3259x; 1.1304x over previous
#include <cuda_runtime.h>
#include <math.h>

// FlowLenia step: SX=SY=256, C=3, K=15, DD=5, DT=0.2, SIGMA=0.65
// out = [newA (256*256*3) | newP (256*256*15)] float32

#define NX 256
#define NC 3
#define NK 15
#define NP 8
#define DTc 0.2f
#define SIGMAc 0.65f
#define MAc 4.35f
#define INV4S2 (1.0f/(4.0f*0.65f*0.65f))
#define SUPP 1.15f
#define IDX(i) ((i) + ((i) >> 4))
#define FSTR 273

// Packed forward spectra: field 0 = FFT2(A0 + i*A1), field 1 = FFT2(A2)
static __device__ float2 g_fZ[2*NX*NX];      // [f][x][y]
static __device__ float2 g_G [NX*NX*NP];     // [x][y][j]
static __device__ float  g_Uc[NX*NX*NC];     // [y][x][c]

__device__ __forceinline__ int rev4(int i) {
    return ((i & 3) << 6) | ((i & 0xC) << 2) | ((i >> 2) & 0xC) | ((i >> 6) & 3);
}
__device__ __forceinline__ float2 cmul(float2 a, float2 b) {
    return make_float2(a.x*b.x - a.y*b.y, a.x*b.y + a.y*b.x);
}
__device__ __forceinline__ void tw_init_smem(float2* tw, int tid, int nthr) {
    for (int j = tid; j < 256; j += nthr) {
        float sv, cv;
        sincospif(-(float)j * (1.0f/128.0f), &sv, &cv);
        tw[j] = make_float2(cv, sv);
    }
}

// In-shared 256-pt radix-4 DIT FFT, 64 threads per FFT, input digit-reversed via IDX.
// __syncthreads at top of each stage (covers producer writes) and at the end.
template<bool INV>
__device__ __forceinline__ void fft256_r4(float2* s, const float2* tw, int t) {
#pragma unroll
    for (int m = 0; m < 4; m++) {
        __syncthreads();
        int q    = 1 << (2*m);
        int p    = t & (q - 1);
        int grp  = t >> (2*m);
        int base = grp*(q << 2) + p;
        int ts   = 64 >> (2*m);
        float2 w1 = tw[p*ts];
        float2 w2 = tw[2*p*ts];
        float2 w3 = tw[3*p*ts];
        if (INV) { w1.y = -w1.y; w2.y = -w2.y; w3.y = -w3.y; }
        float2 x0 = s[IDX(base)];
        float2 t1 = cmul(s[IDX(base +   q)], w1);
        float2 t2 = cmul(s[IDX(base + 2*q)], w2);
        float2 t3 = cmul(s[IDX(base + 3*q)], w3);
        float2 b0 = make_float2(x0.x + t2.x, x0.y + t2.y);
        float2 b1 = make_float2(x0.x - t2.x, x0.y - t2.y);
        float2 b2 = make_float2(t1.x + t3.x, t1.y + t3.y);
        float2 b3 = make_float2(t1.x - t3.x, t1.y - t3.y);
        float2 ib3 = INV ? make_float2(-b3.y, b3.x) : make_float2(b3.y, -b3.x);
        s[IDX(base)]        = make_float2(b0.x + b2.x, b0.y + b2.y);
        s[IDX(base +   q)]  = make_float2(b1.x + ib3.x, b1.y + ib3.y);
        s[IDX(base + 2*q)]  = make_float2(b0.x - b2.x, b0.y - b2.y);
        s[IDX(base + 3*q)]  = make_float2(b1.x - ib3.x, b1.y - ib3.y);
    }
    __syncthreads();
}

// S1: FFT along y of packed fields. grid 256 rows, block (64,2) = 2 fields.
__global__ void s1_fft_y(const float* __restrict__ A) {
    __shared__ float2 sm[2][FSTR];
    __shared__ float2 tw[256];
    int x = blockIdx.x, f = threadIdx.y, t = threadIdx.x;
    int tid = f*64 + t;
    tw_init_smem(tw, tid, 128);
    float2* s = sm[f];
#pragma unroll
    for (int jj = 0; jj < 4; jj++) {
        int i = t + 64*jj;
        const float* a = A + (x*NX + i)*NC;
        float2 v = (f == 0) ? make_float2(a[0], a[1]) : make_float2(a[2], 0.f);
        s[IDX(rev4(i))] = v;
    }
    fft256_r4<false>(s, tw, t);
#pragma unroll
    for (int jj = 0; jj < 4; jj++) {
        int i = t + 64*jj;
        g_fZ[f*NX*NX + x*NX + i] = s[IDX(i)];
    }
}

// S2: FFT along x, 4 ky-columns of one field per block. grid (64, 2), block (64,4).
__global__ void s2_fft_x() {
    __shared__ float2 sm[4][FSTR];
    __shared__ float2 tw[256];
    int f = blockIdx.y, y0 = blockIdx.x * 4;
    int t = threadIdx.x, yl = threadIdx.y;
    int tid = yl*64 + t;
    tw_init_smem(tw, tid, 256);
    int base = f*NX*NX;
    for (int e = tid; e < 1024; e += 256) {
        int x = e >> 2, yy = e & 3;
        sm[yy][IDX(rev4(x))] = g_fZ[base + x*NX + y0 + yy];
    }
    fft256_r4<false>(sm[yl], tw, t);
    for (int e = tid; e < 1024; e += 256) {
        int x = e >> 2, yy = e & 3;
        g_fZ[base + x*NX + y0 + yy] = sm[yy][IDX(x)];
    }
}

// S3: Hermitian unpack + multiply by fK + inverse FFT along y.
// block = one kx row, 4 packed pairs; grid (256, 2).
// fA0[x,y] = 0.5*(Zx + conj(Zm)),  fA1[x,y] = 0.5*(Zx - conj(Zm))/i,
// with Zx = Z01[x,y], Zm = Z01[(-x)&255, (-y)&255];  fA2 = Z2 directly.
__global__ void s3_mul_ifft_y(const float* __restrict__ fKr, const float* __restrict__ fKi) {
    __shared__ float2 sm[4][FSTR];
    __shared__ float2 sZx[NX], sZm[NX], sZ2[NX];
    __shared__ float2 tw[256];
    int x = blockIdx.x, t = threadIdx.x, jl = threadIdx.y;
    int j0 = blockIdx.y * 4;
    int xm = (NX - x) & 255;
    int tid = jl*64 + t;
    tw_init_smem(tw, tid, 256);
    for (int e = tid; e < NX; e += 256) {
        sZx[e] = g_fZ[0*NX*NX + x*NX + e];
        sZm[e] = g_fZ[0*NX*NX + xm*NX + e];
        sZ2[e] = g_fZ[1*NX*NX + x*NX + e];
    }
    __syncthreads();
    for (int e = tid; e < 1024; e += 256) {
        int y = e >> 2, jj = e & 3;
        int ym = (NX - y) & 255;
        float2 Zx = sZx[y], Zm = sZm[ym];
        float2 fa[3];
        fa[0] = make_float2(0.5f*(Zx.x + Zm.x), 0.5f*(Zx.y - Zm.y));
        fa[1] = make_float2(0.5f*(Zx.y + Zm.y), 0.5f*(Zm.x - Zx.x));
        fa[2] = sZ2[y];
        int k1 = 2*(j0 + jj);
        int idx = (x*NX + y)*NK;
        float2 a1 = fa[k1 % NC];
        float kr = fKr[idx + k1], ki = fKi[idx + k1];
        float2 H = make_float2(kr*a1.x - ki*a1.y, kr*a1.y + ki*a1.x);
        if (k1 + 1 < NK) {
            float2 a2 = fa[(k1+1) % NC];
            float kr2 = fKr[idx + k1 + 1], ki2 = fKi[idx + k1 + 1];
            float zr = kr2*a2.x - ki2*a2.y;
            float zi = kr2*a2.y + ki2*a2.x;
            H.x -= zi; H.y += zr;
        }
        sm[jj][IDX(rev4(y))] = H;
    }
    fft256_r4<true>(sm[jl], tw, t);
    for (int e = tid; e < 1024; e += 256) {
        int y = e >> 2, jj = e & 3;
        g_G[(x*NX + y)*NP + j0 + jj] = sm[jj][IDX(y)];
    }
}

// S4: inverse FFT along x + growth*P + channel-sum, fused. block = one y, 8 pairs.
__global__ void s4_ifft_x_growth(const float* __restrict__ P,
                                 const float* __restrict__ mArr,
                                 const float* __restrict__ sArr) {
    __shared__ float2 sm[NP][FSTR];
    __shared__ float  sP[NX*17];
    __shared__ float2 tw[256];
    int y = blockIdx.x, t = threadIdx.x, j = threadIdx.y;
    int tid = j*64 + t;
    tw_init_smem(tw, tid, 512);
    for (int e = tid; e < 2048; e += 512) {
        int xx = e >> 3, jj = e & 7;
        sm[jj][IDX(rev4(xx))] = g_G[(xx*NX + y)*NP + jj];
    }
    for (int e = tid; e < NX*NK; e += 512) {
        int xx = e / NK, k = e - xx*NK;
        sP[xx*17 + k] = P[(xx*NX + y)*NK + k];
    }
    fft256_r4<true>(sm[j], tw, t);

    int k1 = 2*j, k2 = 2*j + 1;
    float m1 = mArr[k1], s1 = sArr[k1];
    float inv1 = 1.f / (2.f * s1 * s1);
    float m2 = 0.f, inv2 = 0.f;
    if (k2 < NK) { m2 = mArr[k2]; float s2 = sArr[k2]; inv2 = 1.f / (2.f * s2 * s2); }
#pragma unroll
    for (int jj2 = 0; jj2 < 4; jj2++) {
        int xx = t + 64*jj2;
        float2 v = sm[j][IDX(xx)];
        float u1 = v.x * (1.f / 65536.f);
        float d1 = u1 - m1;
        sP[xx*17 + k1] *= (2.f * expf(-d1*d1*inv1) - 1.f);
        if (k2 < NK) {
            float u2 = v.y * (1.f / 65536.f);
            float d2 = u2 - m2;
            sP[xx*17 + k2] *= (2.f * expf(-d2*d2*inv2) - 1.f);
        }
    }
    __syncthreads();
    for (int e = tid; e < NX*NC; e += 512) {
        int xx = e / NC, c = e - xx*NC;
        const float* u = sP + xx*17;
        g_Uc[(y*NX + xx)*NC + c] = u[c] + u[c+3] + u[c+6] + u[c+9] + u[c+12];
    }
}

// Fused sobel + mus + reintegration. Output tile 8(x) x 16(y) per 128-thread block.
#define TXo 8
#define TYo 16
__global__ void fused_flow(const float* __restrict__ A, const float* __restrict__ P,
                           float* __restrict__ outA, float* __restrict__ outP) {
    __shared__ __align__(16) float rec[240*24];
    __shared__ float sUc[14*22*3];
    __shared__ float sAs[14*22];
    int tid = threadIdx.x;
    int y0 = blockIdx.x * TYo, x0 = blockIdx.y * TXo;

    for (int e = tid; e < 14*22; e += 128) {
        int i = e / 22, j = e - i*22;
        int gx = x0 - 3 + i, gy = y0 - 3 + j;
        float u0 = 0.f, u1 = 0.f, u2 = 0.f, as = 0.f;
        if (gx >= 0 && gx < NX && gy >= 0 && gy < NX) {
            int bU = (gy*NX + gx)*NC;
            u0 = g_Uc[bU]; u1 = g_Uc[bU+1]; u2 = g_Uc[bU+2];
            int bA = (gx*NX + gy)*NC;
            as = A[bA] + A[bA+1] + A[bA+2];
        }
        sUc[e*3+0] = u0; sUc[e*3+1] = u1; sUc[e*3+2] = u2;
        sAs[e] = as;
    }
    __syncthreads();

    for (int e = tid; e < 240; e += 128) {
        int i = e / 20, j = e - i*20;
        int gx = x0 - 2 + i, gy = y0 - 2 + j;
        float* r = rec + e*24;
        if (gx >= 0 && gx < NX && gy >= 0 && gy < NX) {
            int si = i + 1, sj = j + 1;
            int rm = (si-1)*22 + sj, rp = (si+1)*22 + sj, r0 = si*22 + sj;
            float cg0 = (sAs[rp-1] + 2.f*sAs[rp] + sAs[rp+1])
                      - (sAs[rm-1] + 2.f*sAs[rm] + sAs[rm+1]);
            float cg1 = (sAs[rm+1] + 2.f*sAs[r0+1] + sAs[rp+1])
                      - (sAs[rm-1] + 2.f*sAs[r0-1] + sAs[rp-1]);
            int bA = (gx*NX + gy)*NC;
            float p0 = gx + 0.5f, p1 = gy + 0.5f;
#pragma unroll
            for (int c = 0; c < NC; c++) {
                float f0 = (sUc[(rp-1)*3+c] + 2.f*sUc[rp*3+c] + sUc[(rp+1)*3+c])
                         - (sUc[(rm-1)*3+c] + 2.f*sUc[rm*3+c] + sUc[(rm+1)*3+c]);
                float f1 = (sUc[(rm+1)*3+c] + 2.f*sUc[(r0+1)*3+c] + sUc[(rp+1)*3+c])
                         - (sUc[(rm-1)*3+c] + 2.f*sUc[(r0-1)*3+c] + sUc[(rp-1)*3+c]);
                float ac = A[bA + c];
                float ah = ac * 0.5f;
                float alpha = fminf(ah*ah, 1.f);
                float F0 = fminf(fmaxf(f0*(1.f-alpha) - cg0*alpha, -MAc), MAc);
                float F1 = fminf(fmaxf(f1*(1.f-alpha) - cg1*alpha, -MAc), MAc);
                r[c]   = fminf(fmaxf(p0 + DTc*F0, SIGMAc), (float)NX - SIGMAc);
                r[3+c] = fminf(fmaxf(p1 + DTc*F1, SIGMAc), (float)NX - SIGMAc);
                r[6+c] = ac;
            }
        } else {
#pragma unroll
            for (int c = 0; c < 6; c++) r[c] = -1e9f;
            r[6] = r[7] = r[8] = 0.f;
        }
    }
    for (int e = tid; e < 240*NK; e += 128) {
        int pix = e / NK, k = e - pix*NK;
        int i = pix / 20, j = pix - i*20;
        int gx = x0 - 2 + i, gy = y0 - 2 + j;
        float vv = 0.f;
        if (gx >= 0 && gx < NX && gy >= 0 && gy < NX)
            vv = P[(gx*NX + gy)*NK + k];
        rec[pix*24 + 9 + k] = vv;
    }
    __syncthreads();

    int ty = tid & 15, tx = tid >> 4;
    int x = x0 + tx, y = y0 + ty;
    float p0 = x + 0.5f, p1 = y + 0.5f;
    float accA0 = 0.f, accA1 = 0.f, accA2 = 0.f, accW = 0.f;
    float accP[NK];
#pragma unroll
    for (int k = 0; k < NK; k++) accP[k] = 0.f;

#pragma unroll
    for (int dx = -2; dx <= 2; dx++) {
#pragma unroll
        for (int dy = -2; dy <= 2; dy++) {
            int ridx = (tx + 2 - dx)*20 + (ty + 2 - dy);
            const float4* r4 = (const float4*)(rec + ridx*24);
            float4 q0 = r4[0];
            float4 q1 = r4[1];
            float4 q2 = r4[2];
            float s00 = fminf(fmaxf(SUPP - fabsf(p0 - q0.x), 0.f), 1.f);
            float s01 = fminf(fmaxf(SUPP - fabsf(p0 - q0.y), 0.f), 1.f);
            float s02 = fminf(fmaxf(SUPP - fabsf(p0 - q0.z), 0.f), 1.f);
            float s10 = fminf(fmaxf(SUPP - fabsf(p1 - q0.w), 0.f), 1.f);
            float s11 = fminf(fmaxf(SUPP - fabsf(p1 - q1.x), 0.f), 1.f);
            float s12 = fminf(fmaxf(SUPP - fabsf(p1 - q1.y), 0.f), 1.f);
            float v0 = q1.z * (s00*s10*INV4S2);
            float v1 = q1.w * (s01*s11*INV4S2);
            float v2 = q2.x * (s02*s12*INV4S2);
            accA0 += v0; accA1 += v1; accA2 += v2;
            float suma = v0 + v1 + v2;
            if (suma > 0.f) {
                float w = expf(suma) - 1.f;
                accW += w;
                accP[0] += w*q2.y; accP[1] += w*q2.z; accP[2] += w*q2.w;
                float4 q3 = r4[3], q4 = r4[4], q5 = r4[5];
                accP[3] += w*q3.x; accP[4] += w*q3.y; accP[5] += w*q3.z; accP[6] += w*q3.w;
                accP[7] += w*q4.x; accP[8] += w*q4.y; accP[9] += w*q4.z; accP[10] += w*q4.w;
                accP[11] += w*q5.x; accP[12] += w*q5.y; accP[13] += w*q5.z; accP[14] += w*q5.w;
            }
        }
    }

    int o = x*NX + y;
    outA[o*NC + 0] = accA0; outA[o*NC + 1] = accA1; outA[o*NC + 2] = accA2;
    float inv = 1.f / (accW + 1e-10f);
#pragma unroll
    for (int k = 0; k < NK; k++) outP[o*NK + k] = accP[k] * inv;
}

extern "C" void kernel_launch(void* const* d_in, const int* in_sizes, int n_in,
                              void* d_out, int out_size) {
    const float* A   = (const float*)d_in[0];
    const float* P   = (const float*)d_in[1];
    const float* fKr = (const float*)d_in[2];
    const float* fKi = (const float*)d_in[3];
    const float* m   = (const float*)d_in[4];
    const float* s   = (const float*)d_in[5];
    float* outA = (float*)d_out;
    float* outP = outA + NX*NX*NC;

    s1_fft_y         <<<NX, dim3(64, 2)>>>(A);
    s2_fft_x         <<<dim3(64, 2), dim3(64, 4)>>>();
    s3_mul_ifft_y    <<<dim3(NX, 2), dim3(64, 4)>>>(fKr, fKi);
    s4_ifft_x_growth <<<NX, dim3(64, NP)>>>(P, m, s);
    fused_flow       <<<dim3(16, 32), 128>>>(A, P, outA, outP);
}

// round 11
// speedup vs baseline: 1.4023x; 1.0576x over previous
#include <cuda_runtime.h>
#include <math.h>

// FlowLenia step: SX=SY=256, C=3, K=15, DD=5, DT=0.2, SIGMA=0.65
// out = [newA (256*256*3) | newP (256*256*15)] float32

#define NX 256
#define NC 3
#define NK 15
#define NP 8
#define DTc 0.2f
#define SIGMAc 0.65f
#define MAc 4.35f
#define INV4S2 (1.0f/(4.0f*0.65f*0.65f))
#define SUPP 1.15f
#define IDX(i) ((i) + ((i) >> 4))
#define FSTR 273
#define RSTR 28                  // record stride (24 used + 4 pad, conflict-free LDS.128)

static __device__ float2 g_tw[256];          // twiddles, filled by s1 block 0
// Packed forward spectra: field 0 = FFT2(A0 + i*A1), field 1 = FFT2(A2)
static __device__ float2 g_fZ[2*NX*NX];      // [f][x][y]
static __device__ float2 g_G [NX*NX*NP];     // [x][y][j]
static __device__ float  g_Uc[NX*NX*NC];     // [y][x][c]

__device__ __forceinline__ int rev4(int i) {
    return ((i & 3) << 6) | ((i & 0xC) << 2) | ((i >> 2) & 0xC) | ((i >> 6) & 3);
}
__device__ __forceinline__ float2 cmul(float2 a, float2 b) {
    return make_float2(a.x*b.x - a.y*b.y, a.x*b.y + a.y*b.x);
}
// load twiddle table from global (filled by s1)
__device__ __forceinline__ void tw_load_smem(float2* tw, int tid, int nthr) {
    for (int j = tid; j < 256; j += nthr) tw[j] = g_tw[j];
}

// In-shared 256-pt radix-4 DIT FFT, 64 threads per FFT, input digit-reversed via IDX.
// Stage 0 specialized (all twiddles == 1). __syncthreads at top of each stage and at end.
template<bool INV>
__device__ __forceinline__ void fft256_r4(float2* s, const float2* tw, int t) {
    // stage m=0: q=1, p=0 -> w1=w2=w3=1
    __syncthreads();
    {
        int base = t << 2;
        float2 x0 = s[IDX(base)];
        float2 t1 = s[IDX(base + 1)];
        float2 t2 = s[IDX(base + 2)];
        float2 t3 = s[IDX(base + 3)];
        float2 b0 = make_float2(x0.x + t2.x, x0.y + t2.y);
        float2 b1 = make_float2(x0.x - t2.x, x0.y - t2.y);
        float2 b2 = make_float2(t1.x + t3.x, t1.y + t3.y);
        float2 b3 = make_float2(t1.x - t3.x, t1.y - t3.y);
        float2 ib3 = INV ? make_float2(-b3.y, b3.x) : make_float2(b3.y, -b3.x);
        s[IDX(base)]     = make_float2(b0.x + b2.x, b0.y + b2.y);
        s[IDX(base + 1)] = make_float2(b1.x + ib3.x, b1.y + ib3.y);
        s[IDX(base + 2)] = make_float2(b0.x - b2.x, b0.y - b2.y);
        s[IDX(base + 3)] = make_float2(b1.x - ib3.x, b1.y - ib3.y);
    }
#pragma unroll
    for (int m = 1; m < 4; m++) {
        __syncthreads();
        int q    = 1 << (2*m);
        int p    = t & (q - 1);
        int grp  = t >> (2*m);
        int base = grp*(q << 2) + p;
        int ts   = 64 >> (2*m);
        float2 w1 = tw[p*ts];
        float2 w2 = tw[2*p*ts];
        float2 w3 = tw[3*p*ts];
        if (INV) { w1.y = -w1.y; w2.y = -w2.y; w3.y = -w3.y; }
        float2 x0 = s[IDX(base)];
        float2 t1 = cmul(s[IDX(base +   q)], w1);
        float2 t2 = cmul(s[IDX(base + 2*q)], w2);
        float2 t3 = cmul(s[IDX(base + 3*q)], w3);
        float2 b0 = make_float2(x0.x + t2.x, x0.y + t2.y);
        float2 b1 = make_float2(x0.x - t2.x, x0.y - t2.y);
        float2 b2 = make_float2(t1.x + t3.x, t1.y + t3.y);
        float2 b3 = make_float2(t1.x - t3.x, t1.y - t3.y);
        float2 ib3 = INV ? make_float2(-b3.y, b3.x) : make_float2(b3.y, -b3.x);
        s[IDX(base)]        = make_float2(b0.x + b2.x, b0.y + b2.y);
        s[IDX(base +   q)]  = make_float2(b1.x + ib3.x, b1.y + ib3.y);
        s[IDX(base + 2*q)]  = make_float2(b0.x - b2.x, b0.y - b2.y);
        s[IDX(base + 3*q)]  = make_float2(b1.x - ib3.x, b1.y - ib3.y);
    }
    __syncthreads();
}

// S1: FFT along y of packed fields. grid 256 rows, block (64,2) = 2 fields.
// Computes twiddles via sincospif; block 0 also publishes g_tw for s2-s4.
__global__ void s1_fft_y(const float* __restrict__ A) {
    __shared__ float2 sm[2][FSTR];
    __shared__ float2 tw[256];
    int x = blockIdx.x, f = threadIdx.y, t = threadIdx.x;
    int tid = f*64 + t;
    for (int j = tid; j < 256; j += 128) {
        float sv, cv;
        sincospif(-(float)j * (1.0f/128.0f), &sv, &cv);
        float2 v = make_float2(cv, sv);
        tw[j] = v;
        if (x == 0) g_tw[j] = v;
    }
    float2* s = sm[f];
#pragma unroll
    for (int jj = 0; jj < 4; jj++) {
        int i = t + 64*jj;
        const float* a = A + (x*NX + i)*NC;
        float2 v = (f == 0) ? make_float2(a[0], a[1]) : make_float2(a[2], 0.f);
        s[IDX(rev4(i))] = v;
    }
    fft256_r4<false>(s, tw, t);
#pragma unroll
    for (int jj = 0; jj < 4; jj++) {
        int i = t + 64*jj;
        g_fZ[f*NX*NX + x*NX + i] = s[IDX(i)];
    }
}

// S2: FFT along x, 4 ky-columns of one field per block. grid (64, 2), block (64,4).
__global__ void s2_fft_x() {
    __shared__ float2 sm[4][FSTR];
    __shared__ float2 tw[256];
    int f = blockIdx.y, y0 = blockIdx.x * 4;
    int t = threadIdx.x, yl = threadIdx.y;
    int tid = yl*64 + t;
    tw_load_smem(tw, tid, 256);
    int base = f*NX*NX;
    for (int e = tid; e < 1024; e += 256) {
        int x = e >> 2, yy = e & 3;
        sm[yy][IDX(rev4(x))] = g_fZ[base + x*NX + y0 + yy];
    }
    fft256_r4<false>(sm[yl], tw, t);
    for (int e = tid; e < 1024; e += 256) {
        int x = e >> 2, yy = e & 3;
        g_fZ[base + x*NX + y0 + yy] = sm[yy][IDX(x)];
    }
}

// S3: Hermitian unpack + multiply by fK + inverse FFT along y.
// block = one kx row, 4 packed pairs; grid (256, 2).
// fA0[x,y] = 0.5*(Zx + conj(Zm)),  fA1[x,y] = 0.5*(Zx - conj(Zm))/i,
// with Zx = Z01[x,y], Zm = Z01[(-x)&255, (-y)&255];  fA2 = Z2 directly.
__global__ void s3_mul_ifft_y(const float* __restrict__ fKr, const float* __restrict__ fKi) {
    __shared__ float2 sm[4][FSTR];
    __shared__ float2 sZx[NX], sZm[NX], sZ2[NX];
    __shared__ float2 tw[256];
    int x = blockIdx.x, t = threadIdx.x, jl = threadIdx.y;
    int j0 = blockIdx.y * 4;
    int xm = (NX - x) & 255;
    int tid = jl*64 + t;
    tw_load_smem(tw, tid, 256);
    for (int e = tid; e < NX; e += 256) {
        sZx[e] = g_fZ[0*NX*NX + x*NX + e];
        sZm[e] = g_fZ[0*NX*NX + xm*NX + e];
        sZ2[e] = g_fZ[1*NX*NX + x*NX + e];
    }
    __syncthreads();
    for (int e = tid; e < 1024; e += 256) {
        int y = e >> 2, jj = e & 3;
        int ym = (NX - y) & 255;
        float2 Zx = sZx[y], Zm = sZm[ym];
        float2 fa[3];
        fa[0] = make_float2(0.5f*(Zx.x + Zm.x), 0.5f*(Zx.y - Zm.y));
        fa[1] = make_float2(0.5f*(Zx.y + Zm.y), 0.5f*(Zm.x - Zx.x));
        fa[2] = sZ2[y];
        int k1 = 2*(j0 + jj);
        int idx = (x*NX + y)*NK;
        float2 a1 = fa[k1 % NC];
        float kr = fKr[idx + k1], ki = fKi[idx + k1];
        float2 H = make_float2(kr*a1.x - ki*a1.y, kr*a1.y + ki*a1.x);
        if (k1 + 1 < NK) {
            float2 a2 = fa[(k1+1) % NC];
            float kr2 = fKr[idx + k1 + 1], ki2 = fKi[idx + k1 + 1];
            float zr = kr2*a2.x - ki2*a2.y;
            float zi = kr2*a2.y + ki2*a2.x;
            H.x -= zi; H.y += zr;
        }
        sm[jj][IDX(rev4(y))] = H;
    }
    fft256_r4<true>(sm[jl], tw, t);
    for (int e = tid; e < 1024; e += 256) {
        int y = e >> 2, jj = e & 3;
        g_G[(x*NX + y)*NP + j0 + jj] = sm[jj][IDX(y)];
    }
}

// S4: inverse FFT along x + growth*P + channel-sum, fused. block = one y, 8 pairs.
__global__ void s4_ifft_x_growth(const float* __restrict__ P,
                                 const float* __restrict__ mArr,
                                 const float* __restrict__ sArr) {
    __shared__ float2 sm[NP][FSTR];
    __shared__ float  sP[NX*17];
    __shared__ float2 tw[256];
    int y = blockIdx.x, t = threadIdx.x, j = threadIdx.y;
    int tid = j*64 + t;
    tw_load_smem(tw, tid, 512);
    for (int e = tid; e < 2048; e += 512) {
        int xx = e >> 3, jj = e & 7;
        sm[jj][IDX(rev4(xx))] = g_G[(xx*NX + y)*NP + jj];
    }
    for (int e = tid; e < NX*NK; e += 512) {
        int xx = e / NK, k = e - xx*NK;
        sP[xx*17 + k] = P[(xx*NX + y)*NK + k];
    }
    fft256_r4<true>(sm[j], tw, t);

    int k1 = 2*j, k2 = 2*j + 1;
    float m1 = mArr[k1], s1 = sArr[k1];
    float inv1 = 1.f / (2.f * s1 * s1);
    float m2 = 0.f, inv2 = 0.f;
    if (k2 < NK) { m2 = mArr[k2]; float s2 = sArr[k2]; inv2 = 1.f / (2.f * s2 * s2); }
#pragma unroll
    for (int jj2 = 0; jj2 < 4; jj2++) {
        int xx = t + 64*jj2;
        float2 v = sm[j][IDX(xx)];
        float u1 = v.x * (1.f / 65536.f);
        float d1 = u1 - m1;
        sP[xx*17 + k1] *= (2.f * expf(-d1*d1*inv1) - 1.f);
        if (k2 < NK) {
            float u2 = v.y * (1.f / 65536.f);
            float d2 = u2 - m2;
            sP[xx*17 + k2] *= (2.f * expf(-d2*d2*inv2) - 1.f);
        }
    }
    __syncthreads();
    for (int e = tid; e < NX*NC; e += 512) {
        int xx = e / NC, c = e - xx*NC;
        const float* u = sP + xx*17;
        g_Uc[(y*NX + xx)*NC + c] = u[c] + u[c+3] + u[c+6] + u[c+9] + u[c+12];
    }
}

// Fused sobel + mus + reintegration. Output tile 8(x) x 16(y) per 128-thread block.
// Records: [mu0(3), mu1(3), A(3), P(15)] in stride-28 slots (conflict-free LDS.128).
#define TXo 8
#define TYo 16
__global__ void fused_flow(const float* __restrict__ A, const float* __restrict__ P,
                           float* __restrict__ outA, float* __restrict__ outP) {
    __shared__ __align__(16) float rec[240*RSTR];
    __shared__ float sUc[14*22*3];
    __shared__ float sAs[14*22];
    int tid = threadIdx.x;
    int y0 = blockIdx.x * TYo, x0 = blockIdx.y * TXo;

    for (int e = tid; e < 14*22; e += 128) {
        int i = e / 22, j = e - i*22;
        int gx = x0 - 3 + i, gy = y0 - 3 + j;
        float u0 = 0.f, u1 = 0.f, u2 = 0.f, as = 0.f;
        if (gx >= 0 && gx < NX && gy >= 0 && gy < NX) {
            int bU = (gy*NX + gx)*NC;
            u0 = g_Uc[bU]; u1 = g_Uc[bU+1]; u2 = g_Uc[bU+2];
            int bA = (gx*NX + gy)*NC;
            as = A[bA] + A[bA+1] + A[bA+2];
        }
        sUc[e*3+0] = u0; sUc[e*3+1] = u1; sUc[e*3+2] = u2;
        sAs[e] = as;
    }
    __syncthreads();

    for (int e = tid; e < 240; e += 128) {
        int i = e / 20, j = e - i*20;
        int gx = x0 - 2 + i, gy = y0 - 2 + j;
        float* r = rec + e*RSTR;
        if (gx >= 0 && gx < NX && gy >= 0 && gy < NX) {
            int si = i + 1, sj = j + 1;
            int rm = (si-1)*22 + sj, rp = (si+1)*22 + sj, r0 = si*22 + sj;
            float cg0 = (sAs[rp-1] + 2.f*sAs[rp] + sAs[rp+1])
                      - (sAs[rm-1] + 2.f*sAs[rm] + sAs[rm+1]);
            float cg1 = (sAs[rm+1] + 2.f*sAs[r0+1] + sAs[rp+1])
                      - (sAs[rm-1] + 2.f*sAs[r0-1] + sAs[rp-1]);
            int bA = (gx*NX + gy)*NC;
            float p0 = gx + 0.5f, p1 = gy + 0.5f;
#pragma unroll
            for (int c = 0; c < NC; c++) {
                float f0 = (sUc[(rp-1)*3+c] + 2.f*sUc[rp*3+c] + sUc[(rp+1)*3+c])
                         - (sUc[(rm-1)*3+c] + 2.f*sUc[rm*3+c] + sUc[(rm+1)*3+c]);
                float f1 = (sUc[(rm+1)*3+c] + 2.f*sUc[(r0+1)*3+c] + sUc[(rp+1)*3+c])
                         - (sUc[(rm-1)*3+c] + 2.f*sUc[(r0-1)*3+c] + sUc[(rp-1)*3+c]);
                float ac = A[bA + c];
                float ah = ac * 0.5f;
                float alpha = fminf(ah*ah, 1.f);
                float F0 = fminf(fmaxf(f0*(1.f-alpha) - cg0*alpha, -MAc), MAc);
                float F1 = fminf(fmaxf(f1*(1.f-alpha) - cg1*alpha, -MAc), MAc);
                r[c]   = fminf(fmaxf(p0 + DTc*F0, SIGMAc), (float)NX - SIGMAc);
                r[3+c] = fminf(fmaxf(p1 + DTc*F1, SIGMAc), (float)NX - SIGMAc);
                r[6+c] = ac;
            }
        } else {
#pragma unroll
            for (int c = 0; c < 6; c++) r[c] = -1e9f;
            r[6] = r[7] = r[8] = 0.f;
        }
    }
    for (int e = tid; e < 240*NK; e += 128) {
        int pix = e / NK, k = e - pix*NK;
        int i = pix / 20, j = pix - i*20;
        int gx = x0 - 2 + i, gy = y0 - 2 + j;
        float vv = 0.f;
        if (gx >= 0 && gx < NX && gy >= 0 && gy < NX)
            vv = P[(gx*NX + gy)*NK + k];
        rec[pix*RSTR + 9 + k] = vv;
    }
    __syncthreads();

    int ty = tid & 15, tx = tid >> 4;
    int x = x0 + tx, y = y0 + ty;
    float p0 = x + 0.5f, p1 = y + 0.5f;
    float accA0 = 0.f, accA1 = 0.f, accA2 = 0.f, accW = 0.f;
    float accP[NK];
#pragma unroll
    for (int k = 0; k < NK; k++) accP[k] = 0.f;

#pragma unroll
    for (int dx = -2; dx <= 2; dx++) {
#pragma unroll
        for (int dy = -2; dy <= 2; dy++) {
            int ridx = (tx + 2 - dx)*20 + (ty + 2 - dy);
            const float4* r4 = (const float4*)(rec + ridx*RSTR);
            float4 q0 = r4[0];
            float4 q1 = r4[1];
            float4 q2 = r4[2];
            float s00 = fminf(fmaxf(SUPP - fabsf(p0 - q0.x), 0.f), 1.f);
            float s01 = fminf(fmaxf(SUPP - fabsf(p0 - q0.y), 0.f), 1.f);
            float s02 = fminf(fmaxf(SUPP - fabsf(p0 - q0.z), 0.f), 1.f);
            float s10 = fminf(fmaxf(SUPP - fabsf(p1 - q0.w), 0.f), 1.f);
            float s11 = fminf(fmaxf(SUPP - fabsf(p1 - q1.x), 0.f), 1.f);
            float s12 = fminf(fmaxf(SUPP - fabsf(p1 - q1.y), 0.f), 1.f);
            float v0 = q1.z * (s00*s10*INV4S2);
            float v1 = q1.w * (s01*s11*INV4S2);
            float v2 = q2.x * (s02*s12*INV4S2);
            accA0 += v0; accA1 += v1; accA2 += v2;
            float suma = v0 + v1 + v2;
            if (suma > 0.f) {
                float w = expf(suma) - 1.f;
                accW += w;
                accP[0] += w*q2.y; accP[1] += w*q2.z; accP[2] += w*q2.w;
                float4 q3 = r4[3], q4 = r4[4], q5 = r4[5];
                accP[3] += w*q3.x; accP[4] += w*q3.y; accP[5] += w*q3.z; accP[6] += w*q3.w;
                accP[7] += w*q4.x; accP[8] += w*q4.y; accP[9] += w*q4.z; accP[10] += w*q4.w;
                accP[11] += w*q5.x; accP[12] += w*q5.y; accP[13] += w*q5.z; accP[14] += w*q5.w;
            }
        }
    }

    int o = x*NX + y;
    outA[o*NC + 0] = accA0; outA[o*NC + 1] = accA1; outA[o*NC + 2] = accA2;
    float inv = 1.f / (accW + 1e-10f);
#pragma unroll
    for (int k = 0; k < NK; k++) outP[o*NK + k] = accP[k] * inv;
}

extern "C" void kernel_launch(void* const* d_in, const int* in_sizes, int n_in,
                              void* d_out, int out_size) {
    const float* A   = (const float*)d_in[0];
    const float* P   = (const float*)d_in[1];
    const float* fKr = (const float*)d_in[2];
    const float* fKi = (const float*)d_in[3];
    const float* m   = (const float*)d_in[4];
    const float* s   = (const float*)d_in[5];
    float* outA = (float*)d_out;
    float* outP = outA + NX*NX*NC;

    s1_fft_y         <<<NX, dim3(64, 2)>>>(A);
    s2_fft_x         <<<dim3(64, 2), dim3(64, 4)>>>();
    s3_mul_ifft_y    <<<dim3(NX, 2), dim3(64, 4)>>>(fKr, fKi);
    s4_ifft_x_growth <<<NX, dim3(64, NP)>>>(P, m, s);
    fused_flow       <<<dim3(16, 32), 128>>>(A, P, outA, outP);
}